// round 2
// baseline (speedup 1.0000x reference)
#include <cuda_runtime.h>
#include <cstdint>

#define N_NODES 10000
#define N_EDGES 160000

// ---------------- scratch (device globals; no allocs allowed) ----------------
// feat layout per node (320): [0:128) feat0[u]; [128:320) feat1[u][i] (i fastest)
// self: same layout, pre-scaled by cos(angle)
// g_h: h2 transposed [k][e]  (k in 0..63)
// g_agg layout per node (768):
//   [0:128)    mid0a[u]
//   [128:192)  mid0b[u]
//   [192:576)  mid1a SoA: 192 + i*128 + u
//   [576:768)  mid1b SoA: 576 + i*64  + u
__device__ float g_feat[N_NODES * 320];
__device__ float g_self[N_NODES * 320];
__device__ float g_h[64 * N_EDGES];
__device__ float g_agg[N_NODES * 768];

__device__ __forceinline__ float gelu_tanh(float x) {
    float x3 = x * x * x;
    return 0.5f * x * (1.0f + tanhf(0.7978845608028654f * (x + 0.044715f * x3)));
}

__device__ __forceinline__ void red4(float* p, float a, float b, float c, float d) {
    asm volatile("red.global.add.v4.f32 [%0], {%1,%2,%3,%4};"
                 :: "l"(p), "f"(a), "f"(b), "f"(c), "f"(d) : "memory");
}

// ---------------- kernel 0: zero the aggregation buffer ----------------
__global__ void zero_agg_kernel() {
    int i = blockIdx.x * blockDim.x + threadIdx.x;   // 1,920,000 float4
    float4* p = (float4*)g_agg;
    p[i] = make_float4(0.f, 0.f, 0.f, 0.f);
}

// ---------------- kernel 1: node pre-transform ----------------
// feat0 = x0@Wa0/sqrt128 ; feat1_i = x1_i@Wa1/8 ; self = cos * (x@Wb)/...
__global__ void node_pre_kernel(const float* __restrict__ node_input,
                                const float* __restrict__ Wa0,
                                const float* __restrict__ Wa1,
                                const float* __restrict__ Wb0,
                                const float* __restrict__ Wb1) {
    extern __shared__ float sm[];
    float* sWa0 = sm;                 // 16384
    float* sWb0 = sm + 16384;         // 16384
    float* sWa1 = sm + 32768;         // 4096
    float* sWb1 = sm + 36864;         // 4096
    float* xs0  = sm + 40960;         // 8*128   x0 per node
    float* xs1  = sm + 40960 + 1024;  // 8*192   [node][i*64 + v]

    const int tid = threadIdx.x;
    const float sA0 = 0.08838834764831845f;            // 1/sqrt(128)
    const float sA1 = 0.125f;                          // 1/sqrt(64)
    const float cc  = 0.9238795325112867f;             // cos(pi/8)

    for (int i = tid; i < 16384; i += 128) {
        sWa0[i] = Wa0[i] * sA0;
        sWb0[i] = Wb0[i] * (cc * sA0);
    }
    for (int i = tid; i < 4096; i += 128) {
        sWa1[i] = Wa1[i] * sA1;
        sWb1[i] = Wb1[i] * (cc * sA1);
    }

    for (int g = 0; g < 8; g++) {
        int gi = blockIdx.x * 8 + g;
        if (gi >= 1250) break;
        int nb = gi * 8;   // 8 nodes per group

        __syncthreads();
        // stage x: x0 -> xs0[node][v]; x1 -> xs1[node][i*64+v]
        for (int idx = tid; idx < 8 * 320; idx += 128) {
            int nd = idx / 320, q = idx % 320;
            float v = node_input[(size_t)(nb + nd) * 320 + q];
            if (q < 128) xs0[nd * 128 + q] = v;
            else {
                int vi = q - 128;
                xs1[nd * 192 + (vi % 3) * 64 + (vi / 3)] = v;
            }
        }
        __syncthreads();

        // ---- role A: feat0/self0, u = tid, 8 nodes register-tiled ----
        {
            const int u = tid;
            float aF[8], aS[8];
            #pragma unroll
            for (int n = 0; n < 8; n++) { aF[n] = 0.f; aS[n] = 0.f; }
            for (int v = 0; v < 128; v += 4) {
                float4 xq[8];
                #pragma unroll
                for (int n = 0; n < 8; n++) xq[n] = *(const float4*)&xs0[n * 128 + v];
                float wA0 = sWa0[(v + 0) * 128 + u], wB0 = sWb0[(v + 0) * 128 + u];
                float wA1 = sWa0[(v + 1) * 128 + u], wB1 = sWb0[(v + 1) * 128 + u];
                float wA2 = sWa0[(v + 2) * 128 + u], wB2 = sWb0[(v + 2) * 128 + u];
                float wA3 = sWa0[(v + 3) * 128 + u], wB3 = sWb0[(v + 3) * 128 + u];
                #pragma unroll
                for (int n = 0; n < 8; n++) {
                    aF[n] = fmaf(xq[n].x, wA0, aF[n]); aS[n] = fmaf(xq[n].x, wB0, aS[n]);
                    aF[n] = fmaf(xq[n].y, wA1, aF[n]); aS[n] = fmaf(xq[n].y, wB1, aS[n]);
                    aF[n] = fmaf(xq[n].z, wA2, aF[n]); aS[n] = fmaf(xq[n].z, wB2, aS[n]);
                    aF[n] = fmaf(xq[n].w, wA3, aF[n]); aS[n] = fmaf(xq[n].w, wB3, aS[n]);
                }
            }
            #pragma unroll
            for (int n = 0; n < 8; n++) {
                g_feat[(size_t)(nb + n) * 320 + u] = aF[n];
                g_self[(size_t)(nb + n) * 320 + u] = aS[n];
            }
        }

        // ---- role B: feat1/self1, u = tid&63, 4 nodes per half-block ----
        {
            const int u = tid & 63;
            const int n0 = (tid >> 6) * 4;   // 0 or 4
            float aF[4][3], aS[4][3];
            #pragma unroll
            for (int n = 0; n < 4; n++)
                #pragma unroll
                for (int i2 = 0; i2 < 3; i2++) { aF[n][i2] = 0.f; aS[n][i2] = 0.f; }
            for (int v = 0; v < 64; v += 4) {
                float4 xq[4][3];
                #pragma unroll
                for (int n = 0; n < 4; n++)
                    #pragma unroll
                    for (int i2 = 0; i2 < 3; i2++)
                        xq[n][i2] = *(const float4*)&xs1[(n0 + n) * 192 + i2 * 64 + v];
                float wA0 = sWa1[(v + 0) * 64 + u], wB0 = sWb1[(v + 0) * 64 + u];
                float wA1 = sWa1[(v + 1) * 64 + u], wB1 = sWb1[(v + 1) * 64 + u];
                float wA2 = sWa1[(v + 2) * 64 + u], wB2 = sWb1[(v + 2) * 64 + u];
                float wA3 = sWa1[(v + 3) * 64 + u], wB3 = sWb1[(v + 3) * 64 + u];
                #pragma unroll
                for (int n = 0; n < 4; n++) {
                    #pragma unroll
                    for (int i2 = 0; i2 < 3; i2++) {
                        aF[n][i2] = fmaf(xq[n][i2].x, wA0, aF[n][i2]); aS[n][i2] = fmaf(xq[n][i2].x, wB0, aS[n][i2]);
                        aF[n][i2] = fmaf(xq[n][i2].y, wA1, aF[n][i2]); aS[n][i2] = fmaf(xq[n][i2].y, wB1, aS[n][i2]);
                        aF[n][i2] = fmaf(xq[n][i2].z, wA2, aF[n][i2]); aS[n][i2] = fmaf(xq[n][i2].z, wB2, aS[n][i2]);
                        aF[n][i2] = fmaf(xq[n][i2].w, wA3, aF[n][i2]); aS[n][i2] = fmaf(xq[n][i2].w, wB3, aS[n][i2]);
                    }
                }
            }
            #pragma unroll
            for (int n = 0; n < 4; n++)
                #pragma unroll
                for (int i2 = 0; i2 < 3; i2++) {
                    size_t base = (size_t)(nb + n0 + n) * 320 + 128 + u * 3 + i2;
                    g_feat[base] = aF[n][i2];
                    g_self[base] = aS[n][i2];
                }
        }
    }
}

// ---------------- kernel 2: edge MLP (h2 = gelu(gelu(es@M1)@M2)) ----------------
__global__ void edge_mlp_kernel(const float* __restrict__ es_attr,
                                const float* __restrict__ M1,
                                const float* __restrict__ M2) {
    __shared__ float sM1[8 * 64];
    __shared__ float sM2[64 * 64];
    const int tid = threadIdx.x;
    const float s1 = 0.3535533905932738f;  // 1/sqrt(8)
    const float s2 = 0.125f;
    for (int i = tid; i < 512; i += 256)  sM1[i] = M1[i] * s1;
    for (int i = tid; i < 4096; i += 256) sM2[i] = M2[i] * s2;
    __syncthreads();

    const int e = blockIdx.x * 256 + tid;
    float es[8];
    {
        float4 p0 = *(const float4*)&es_attr[(size_t)e * 8];
        float4 p1 = *(const float4*)&es_attr[(size_t)e * 8 + 4];
        es[0] = p0.x; es[1] = p0.y; es[2] = p0.z; es[3] = p0.w;
        es[4] = p1.x; es[5] = p1.y; es[6] = p1.z; es[7] = p1.w;
    }
    float h1[64];
    #pragma unroll
    for (int k = 0; k < 64; k += 4) {
        float ax = 0.f, ay = 0.f, az = 0.f, aw = 0.f;
        #pragma unroll
        for (int j = 0; j < 8; j++) {
            float4 w = *(const float4*)&sM1[j * 64 + k];
            ax = fmaf(es[j], w.x, ax); ay = fmaf(es[j], w.y, ay);
            az = fmaf(es[j], w.z, az); aw = fmaf(es[j], w.w, aw);
        }
        h1[k + 0] = gelu_tanh(ax); h1[k + 1] = gelu_tanh(ay);
        h1[k + 2] = gelu_tanh(az); h1[k + 3] = gelu_tanh(aw);
    }
    #pragma unroll
    for (int k = 0; k < 64; k += 4) {
        float ax = 0.f, ay = 0.f, az = 0.f, aw = 0.f;
        #pragma unroll
        for (int j = 0; j < 64; j++) {
            float4 w = *(const float4*)&sM2[j * 64 + k];
            ax = fmaf(h1[j], w.x, ax); ay = fmaf(h1[j], w.y, ay);
            az = fmaf(h1[j], w.z, az); aw = fmaf(h1[j], w.w, aw);
        }
        g_h[(size_t)(k + 0) * N_EDGES + e] = gelu_tanh(ax);
        g_h[(size_t)(k + 1) * N_EDGES + e] = gelu_tanh(ay);
        g_h[(size_t)(k + 2) * N_EDGES + e] = gelu_tanh(az);
        g_h[(size_t)(k + 3) * N_EDGES + e] = gelu_tanh(aw);
    }
}

// ---------------- kernel 3: fused w-GEMM + tensor-product + scatter ----------------
// tile: 64 edges x 384 cols. thread = (tx: 12 cols, ty: 8 edges) -> 96 regs acc.
__global__ void edge_scatter_kernel(const float* __restrict__ edge_attr,
                                    const float* __restrict__ Wtp0,
                                    const float* __restrict__ Wtp1,
                                    const float* __restrict__ Wtp2,
                                    const float* __restrict__ Wtp3,
                                    const int* __restrict__ edge_src,
                                    const int* __restrict__ edge_dst) {
    extern __shared__ float sm[];
    float* sW = sm;              // 64*384
    float* sH = sm + 24576;      // 64*64 [k][e]
    int*   sSrc = (int*)(sm + 28672);   // 64
    int*   sDst = sSrc + 64;            // 64
    float4* sY  = (float4*)(sDst + 64); // 64

    const int tid = threadIdx.x;
    const float f0 = 0.03125f;                     // (1/8)*(1/4)
    const float f3 = 0.03125f * 0.5773502691896258f; // * 1/sqrt(3)

    for (int i = tid; i < 64 * 384; i += 256) {
        int k = i / 384, j = i % 384;
        float w;
        if (j < 128)      w = Wtp0[k * 128 + j] * f0;
        else if (j < 256) w = Wtp1[k * 128 + (j - 128)] * f0;
        else if (j < 320) w = Wtp2[k * 64 + (j - 256)] * f0;
        else              w = Wtp3[k * 64 + (j - 320)] * f3;
        sW[i] = w;
    }
    const int B = blockIdx.x * 64;
    for (int i = tid; i < 4096; i += 256)
        sH[i] = g_h[(size_t)(i >> 6) * N_EDGES + B + (i & 63)];
    if (tid < 64) {
        int e = B + tid;
        sSrc[tid] = edge_src[e];
        sDst[tid] = edge_dst[e];
        sY[tid] = *(const float4*)&edge_attr[(size_t)e * 4];
    }
    __syncthreads();

    const int tx = tid & 31, ty = tid >> 5;
    const int j0 = tx * 12, eb = ty * 8;

    float acc[8][12];
    #pragma unroll
    for (int a = 0; a < 8; a++)
        #pragma unroll
        for (int b = 0; b < 12; b++) acc[a][b] = 0.f;

    #pragma unroll 2
    for (int k = 0; k < 64; k++) {
        const float* wr = &sW[k * 384 + j0];
        float4 wa = *(const float4*)(wr);
        float4 wb = *(const float4*)(wr + 4);
        float4 wc = *(const float4*)(wr + 8);
        #pragma unroll
        for (int e2 = 0; e2 < 8; e2++) {
            float h = sH[(k << 6) + eb + e2];
            acc[e2][0]  = fmaf(h, wa.x, acc[e2][0]);
            acc[e2][1]  = fmaf(h, wa.y, acc[e2][1]);
            acc[e2][2]  = fmaf(h, wa.z, acc[e2][2]);
            acc[e2][3]  = fmaf(h, wa.w, acc[e2][3]);
            acc[e2][4]  = fmaf(h, wb.x, acc[e2][4]);
            acc[e2][5]  = fmaf(h, wb.y, acc[e2][5]);
            acc[e2][6]  = fmaf(h, wb.z, acc[e2][6]);
            acc[e2][7]  = fmaf(h, wb.w, acc[e2][7]);
            acc[e2][8]  = fmaf(h, wc.x, acc[e2][8]);
            acc[e2][9]  = fmaf(h, wc.y, acc[e2][9]);
            acc[e2][10] = fmaf(h, wc.z, acc[e2][10]);
            acc[e2][11] = fmaf(h, wc.w, acc[e2][11]);
        }
    }

    // epilogue: per edge, per aligned quad of cols -> vector REDs
    #pragma unroll
    for (int e2 = 0; e2 < 8; e2++) {
        const int le = eb + e2;
        const float* fr = g_feat + (size_t)sSrc[le] * 320;
        float* ar = g_agg + (size_t)sDst[le] * 768;
        float4 yv = sY[le];  // y0 = yv.x ; y1 = (yv.y, yv.z, yv.w)
        #pragma unroll
        for (int q = 0; q < 3; q++) {
            int j = j0 + 4 * q;
            float w0 = acc[e2][4 * q + 0], w1 = acc[e2][4 * q + 1];
            float w2 = acc[e2][4 * q + 2], w3 = acc[e2][4 * q + 3];
            if (j < 128) {                 // mid0a = w0 * e0 * y0
                float4 e0v = *(const float4*)(fr + j);
                red4(ar + j, w0 * e0v.x * yv.x, w1 * e0v.y * yv.x,
                             w2 * e0v.z * yv.x, w3 * e0v.w * yv.x);
            } else if (j < 256) {          // mid1a = w1 * e0 * y1_i (SoA by i)
                int u = j - 128;
                float4 e0v = *(const float4*)(fr + u);
                float t0 = w0 * e0v.x, t1 = w1 * e0v.y, t2 = w2 * e0v.z, t3 = w3 * e0v.w;
                red4(ar + 192 + u,       t0 * yv.y, t1 * yv.y, t2 * yv.y, t3 * yv.y);
                red4(ar + 192 + 128 + u, t0 * yv.z, t1 * yv.z, t2 * yv.z, t3 * yv.z);
                red4(ar + 192 + 256 + u, t0 * yv.w, t1 * yv.w, t2 * yv.w, t3 * yv.w);
            } else if (j < 320) {          // mid1b = w2 * e1_i * y0 (SoA by i)
                int u = j - 256;
                const float* p = fr + 128 + 3 * u;
                float4 a = *(const float4*)p;
                float4 b = *(const float4*)(p + 4);
                float4 c = *(const float4*)(p + 8);
                float y0 = yv.x;
                red4(ar + 576 + u,       w0 * a.x * y0, w1 * a.w * y0, w2 * b.z * y0, w3 * c.y * y0);
                red4(ar + 576 + 64 + u,  w0 * a.y * y0, w1 * b.x * y0, w2 * b.w * y0, w3 * c.z * y0);
                red4(ar + 576 + 128 + u, w0 * a.z * y0, w1 * b.y * y0, w2 * c.x * y0, w3 * c.w * y0);
            } else {                       // mid0b = w3 * dot(e1, y1) (1/sqrt3 folded)
                int u = j - 320;
                const float* p = fr + 128 + 3 * u;
                float4 a = *(const float4*)p;
                float4 b = *(const float4*)(p + 4);
                float4 c = *(const float4*)(p + 8);
                float d0 = a.x * yv.y + a.y * yv.z + a.z * yv.w;
                float d1 = a.w * yv.y + b.x * yv.z + b.y * yv.w;
                float d2 = b.z * yv.y + b.w * yv.z + c.x * yv.w;
                float d3 = c.y * yv.y + c.z * yv.z + c.w * yv.w;
                red4(ar + 128 + u, w0 * d0, w1 * d1, w2 * d2, w3 * d3);
            }
        }
    }
}

// ---------------- kernel 4: node post (output GEMM + combine) ----------------
__global__ void node_post_kernel(const float* __restrict__ Wo0,
                                 const float* __restrict__ Wo1,
                                 float* __restrict__ out) {
    extern __shared__ float sm[];
    float* sWo0 = sm;            // 192*128
    float* sWo1 = sm + 24576;    // 192*64
    float* zs   = sm + 36864;    // 4*768

    const int tid = threadIdx.x;
    const float so = 0.3826834323650898f * 0.07216878364870323f; // sin(pi/8)/sqrt(192)
    for (int i = tid; i < 24576; i += 128) sWo0[i] = Wo0[i] * so;
    for (int i = tid; i < 12288; i += 128) sWo1[i] = Wo1[i] * so;

    for (int t = 0; t < 10; t++) {
        int nb = blockIdx.x * 40 + t * 4;
        __syncthreads();
        for (int idx = tid; idx < 768; idx += 128) {
            #pragma unroll
            for (int n = 0; n < 4; n++)
                zs[n * 768 + idx] = g_agg[(size_t)(nb + n) * 768 + idx];
        }
        __syncthreads();

        // conv0: u = tid
        {
            const int u = tid;
            float a0[4] = {0.f, 0.f, 0.f, 0.f};
            for (int v = 0; v < 192; v += 4) {
                float w0 = sWo0[(v + 0) * 128 + u];
                float w1 = sWo0[(v + 1) * 128 + u];
                float w2 = sWo0[(v + 2) * 128 + u];
                float w3 = sWo0[(v + 3) * 128 + u];
                #pragma unroll
                for (int n = 0; n < 4; n++) {
                    float4 zq = *(const float4*)&zs[n * 768 + v];
                    a0[n] = fmaf(zq.x, w0, a0[n]);
                    a0[n] = fmaf(zq.y, w1, a0[n]);
                    a0[n] = fmaf(zq.z, w2, a0[n]);
                    a0[n] = fmaf(zq.w, w3, a0[n]);
                }
            }
            #pragma unroll
            for (int n = 0; n < 4; n++) {
                size_t o = (size_t)(nb + n) * 320 + u;
                out[o] = g_self[o] + a0[n];
            }
        }
        // conv1: u = tid&63, 2 nodes per half
        {
            const int uu = tid & 63;
            const int ns = (tid >> 6) * 2;
            float a1[2][3];
            #pragma unroll
            for (int n = 0; n < 2; n++)
                #pragma unroll
                for (int i2 = 0; i2 < 3; i2++) a1[n][i2] = 0.f;

            for (int v = 0; v < 128; v += 4) {   // mid1a part of z1
                float w0 = sWo1[(v + 0) * 64 + uu];
                float w1 = sWo1[(v + 1) * 64 + uu];
                float w2 = sWo1[(v + 2) * 64 + uu];
                float w3 = sWo1[(v + 3) * 64 + uu];
                #pragma unroll
                for (int n = 0; n < 2; n++) {
                    const float* zb = &zs[(ns + n) * 768 + 192];
                    #pragma unroll
                    for (int i2 = 0; i2 < 3; i2++) {
                        float4 zq = *(const float4*)&zb[i2 * 128 + v];
                        a1[n][i2] = fmaf(zq.x, w0, a1[n][i2]);
                        a1[n][i2] = fmaf(zq.y, w1, a1[n][i2]);
                        a1[n][i2] = fmaf(zq.z, w2, a1[n][i2]);
                        a1[n][i2] = fmaf(zq.w, w3, a1[n][i2]);
                    }
                }
            }
            for (int v = 0; v < 64; v += 4) {    // mid1b part of z1
                float w0 = sWo1[(128 + v + 0) * 64 + uu];
                float w1 = sWo1[(128 + v + 1) * 64 + uu];
                float w2 = sWo1[(128 + v + 2) * 64 + uu];
                float w3 = sWo1[(128 + v + 3) * 64 + uu];
                #pragma unroll
                for (int n = 0; n < 2; n++) {
                    const float* zb = &zs[(ns + n) * 768 + 576];
                    #pragma unroll
                    for (int i2 = 0; i2 < 3; i2++) {
                        float4 zq = *(const float4*)&zb[i2 * 64 + v];
                        a1[n][i2] = fmaf(zq.x, w0, a1[n][i2]);
                        a1[n][i2] = fmaf(zq.y, w1, a1[n][i2]);
                        a1[n][i2] = fmaf(zq.z, w2, a1[n][i2]);
                        a1[n][i2] = fmaf(zq.w, w3, a1[n][i2]);
                    }
                }
            }
            #pragma unroll
            for (int n = 0; n < 2; n++)
                #pragma unroll
                for (int i2 = 0; i2 < 3; i2++) {
                    size_t o = (size_t)(nb + ns + n) * 320 + 128 + uu * 3 + i2;
                    out[o] = g_self[o] + a1[n][i2];
                }
        }
    }
}

// ---------------- launch ----------------
extern "C" void kernel_launch(void* const* d_in, const int* in_sizes, int n_in,
                              void* d_out, int out_size) {
    const float* node_input = (const float*)d_in[0];
    const float* edge_attr  = (const float*)d_in[1];
    const float* edge_sc    = (const float*)d_in[2];
    const float* Wa0 = (const float*)d_in[3];
    const float* Wa1 = (const float*)d_in[4];
    const float* Wb0 = (const float*)d_in[5];
    const float* Wb1 = (const float*)d_in[6];
    const float* M1  = (const float*)d_in[7];
    const float* M2  = (const float*)d_in[8];
    const float* Wtp0 = (const float*)d_in[9];
    const float* Wtp1 = (const float*)d_in[10];
    const float* Wtp2 = (const float*)d_in[11];
    const float* Wtp3 = (const float*)d_in[12];
    const float* Wo0  = (const float*)d_in[13];
    const float* Wo1  = (const float*)d_in[14];
    const int* esrc = (const int*)d_in[15];
    const int* edst = (const int*)d_in[16];
    float* out = (float*)d_out;

    cudaFuncSetAttribute(node_pre_kernel,     cudaFuncAttributeMaxDynamicSharedMemorySize, 174080);
    cudaFuncSetAttribute(edge_scatter_kernel, cudaFuncAttributeMaxDynamicSharedMemorySize, 116224);
    cudaFuncSetAttribute(node_post_kernel,    cudaFuncAttributeMaxDynamicSharedMemorySize, 159744);

    zero_agg_kernel<<<7500, 256>>>();
    node_pre_kernel<<<157, 128, 174080>>>(node_input, Wa0, Wa1, Wb0, Wb1);
    edge_mlp_kernel<<<625, 256>>>(edge_sc, M1, M2);
    edge_scatter_kernel<<<2500, 256, 116224>>>(edge_attr, Wtp0, Wtp1, Wtp2, Wtp3, esrc, edst);
    node_post_kernel<<<250, 128, 159744>>>(Wo0, Wo1, out);
}

// round 3
// speedup vs baseline: 2.2858x; 2.2858x over previous
#include <cuda_runtime.h>
#include <cstdint>

#define N_NODES 10000
#define N_EDGES 160000

// ---------------- scratch ----------------
// feat layout per node (320): [0:128) feat0[u]; [128:320) feat1[u][i] (i fastest)
// self: same layout, pre-scaled by cos(angle)
// g_h: h2 transposed [k][e]
// g_agg per node (768): [0:128) mid0a | [128:192) mid0b | [192:576) mid1a SoA (192+i*128+u) | [576:768) mid1b SoA (576+i*64+u)
__device__ float g_feat[N_NODES * 320];
__device__ float g_self[N_NODES * 320];
__device__ float g_h[64 * N_EDGES];
__device__ float g_agg[N_NODES * 768];

__device__ __forceinline__ float gelu_tanh(float x) {
    float x3 = x * x * x;
    return 0.5f * x * (1.0f + tanhf(0.7978845608028654f * (x + 0.044715f * x3)));
}

__device__ __forceinline__ void red4(float* p, float a, float b, float c, float d) {
    asm volatile("red.global.add.v4.f32 [%0], {%1,%2,%3,%4};"
                 :: "l"(p), "f"(a), "f"(b), "f"(c), "f"(d) : "memory");
}

// ---------------- kernel 0: zero agg ----------------
__global__ void zero_agg_kernel() {
    int i = blockIdx.x * blockDim.x + threadIdx.x;   // 1,920,000 float4
    float4* p = (float4*)g_agg;
    p[i] = make_float4(0.f, 0.f, 0.f, 0.f);
}

// ---------------- kernel 1: node pre (streaming-W GEMMs) ----------------
// blocks [0,625): GEMM0 — 16 nodes, 256 cols (128 feat0/Wa0 | 128 self0/Wb0)
// blocks [625,1250): GEMM1 — 16 nodes (2 halves of 8), 128 cols (64 feat1/Wa1 | 64 self1/Wb1), 3 comps
__global__ __launch_bounds__(256) void node_pre_kernel(const float* __restrict__ node_input,
                                const float* __restrict__ Wa0,
                                const float* __restrict__ Wa1,
                                const float* __restrict__ Wb0,
                                const float* __restrict__ Wb1) {
    extern __shared__ float sm[];
    const int tid = threadIdx.x;
    const float sA0 = 0.08838834764831845f;            // 1/sqrt(128)
    const float sA1 = 0.125f;                          // 1/sqrt(64)
    const float cc  = 0.9238795325112867f;             // cos(pi/8)

    if (blockIdx.x < 625) {
        // ---- GEMM0 ----
        const int nb = blockIdx.x * 16;
        float* xs0 = sm;                               // 16 x 128
        for (int i = tid; i < 16 * 128; i += 256)
            xs0[i] = node_input[(size_t)(nb + (i >> 7)) * 320 + (i & 127)];
        __syncthreads();

        const int sel = tid >> 7;          // 0: Wa0->feat, 1: Wb0->self
        const int u   = tid & 127;
        const float* W = sel ? Wb0 : Wa0;
        const float sc = sel ? (cc * sA0) : sA0;
        float acc[16];
        #pragma unroll
        for (int n = 0; n < 16; n++) acc[n] = 0.f;
        #pragma unroll 4
        for (int v = 0; v < 128; v++) {
            float w = W[v * 128 + u] * sc;
            #pragma unroll
            for (int n = 0; n < 16; n++)
                acc[n] = fmaf(xs0[n * 128 + v], w, acc[n]);
        }
        float* dst = sel ? g_self : g_feat;
        #pragma unroll
        for (int n = 0; n < 16; n++)
            dst[(size_t)(nb + n) * 320 + u] = acc[n];
    } else {
        // ---- GEMM1 ----
        const int nb = (blockIdx.x - 625) * 16;
        float* xs1 = sm;                               // 16 x 3 x 64 : [n*192 + i*64 + v]
        for (int idx = tid; idx < 16 * 192; idx += 256) {
            int n = idx / 192, r = idx % 192;
            int i = r >> 6, v = r & 63;
            xs1[idx] = node_input[(size_t)(nb + n) * 320 + 128 + v * 3 + i];
        }
        __syncthreads();

        const int nh  = tid >> 7;          // node half: 8 nodes
        const int lcl = tid & 127;
        const int sel = lcl >> 6;          // 0: Wa1->feat, 1: Wb1->self
        const int u   = lcl & 63;
        const float* W = sel ? Wb1 : Wa1;
        const float sc = sel ? (cc * sA1) : sA1;
        float acc[8][3];
        #pragma unroll
        for (int n = 0; n < 8; n++)
            #pragma unroll
            for (int i = 0; i < 3; i++) acc[n][i] = 0.f;
        #pragma unroll 4
        for (int v = 0; v < 64; v++) {
            float w = W[v * 64 + u] * sc;
            #pragma unroll
            for (int n = 0; n < 8; n++) {
                const float* xb = &xs1[(nh * 8 + n) * 192 + v];
                acc[n][0] = fmaf(xb[0],   w, acc[n][0]);
                acc[n][1] = fmaf(xb[64],  w, acc[n][1]);
                acc[n][2] = fmaf(xb[128], w, acc[n][2]);
            }
        }
        float* dst = sel ? g_self : g_feat;
        #pragma unroll
        for (int n = 0; n < 8; n++)
            #pragma unroll
            for (int i = 0; i < 3; i++)
                dst[(size_t)(nb + nh * 8 + n) * 320 + 128 + u * 3 + i] = acc[n][i];
    }
}

// ---------------- kernel 2: edge MLP ----------------
__global__ void edge_mlp_kernel(const float* __restrict__ es_attr,
                                const float* __restrict__ M1,
                                const float* __restrict__ M2) {
    __shared__ float sM1[8 * 64];
    __shared__ float sM2[64 * 64];
    const int tid = threadIdx.x;
    const float s1 = 0.3535533905932738f;  // 1/sqrt(8)
    const float s2 = 0.125f;
    for (int i = tid; i < 512; i += 256)  sM1[i] = M1[i] * s1;
    for (int i = tid; i < 4096; i += 256) sM2[i] = M2[i] * s2;
    __syncthreads();

    const int e = blockIdx.x * 256 + tid;
    float es[8];
    {
        float4 p0 = *(const float4*)&es_attr[(size_t)e * 8];
        float4 p1 = *(const float4*)&es_attr[(size_t)e * 8 + 4];
        es[0] = p0.x; es[1] = p0.y; es[2] = p0.z; es[3] = p0.w;
        es[4] = p1.x; es[5] = p1.y; es[6] = p1.z; es[7] = p1.w;
    }
    float h1[64];
    #pragma unroll
    for (int k = 0; k < 64; k += 4) {
        float ax = 0.f, ay = 0.f, az = 0.f, aw = 0.f;
        #pragma unroll
        for (int j = 0; j < 8; j++) {
            float4 w = *(const float4*)&sM1[j * 64 + k];
            ax = fmaf(es[j], w.x, ax); ay = fmaf(es[j], w.y, ay);
            az = fmaf(es[j], w.z, az); aw = fmaf(es[j], w.w, aw);
        }
        h1[k + 0] = gelu_tanh(ax); h1[k + 1] = gelu_tanh(ay);
        h1[k + 2] = gelu_tanh(az); h1[k + 3] = gelu_tanh(aw);
    }
    #pragma unroll
    for (int k = 0; k < 64; k += 4) {
        float ax = 0.f, ay = 0.f, az = 0.f, aw = 0.f;
        #pragma unroll
        for (int j = 0; j < 64; j++) {
            float4 w = *(const float4*)&sM2[j * 64 + k];
            ax = fmaf(h1[j], w.x, ax); ay = fmaf(h1[j], w.y, ay);
            az = fmaf(h1[j], w.z, az); aw = fmaf(h1[j], w.w, aw);
        }
        g_h[(size_t)(k + 0) * N_EDGES + e] = gelu_tanh(ax);
        g_h[(size_t)(k + 1) * N_EDGES + e] = gelu_tanh(ay);
        g_h[(size_t)(k + 2) * N_EDGES + e] = gelu_tanh(az);
        g_h[(size_t)(k + 3) * N_EDGES + e] = gelu_tanh(aw);
    }
}

// ---------------- kernel 3: fused w-GEMM + TP + scatter (column-segmented) ----------------
// grid = (2500, 3). blockIdx.y = column segment of 128: [0,128) | [128,256) | [256,384)
// block 256: tx = tid&31 -> 4 cols, ty = tid>>5 -> 8 edges
__global__ __launch_bounds__(256, 3)
void edge_scatter_kernel(const float* __restrict__ edge_attr,
                         const float* __restrict__ Wtp0,
                         const float* __restrict__ Wtp1,
                         const float* __restrict__ Wtp2,
                         const float* __restrict__ Wtp3,
                         const int* __restrict__ edge_src,
                         const int* __restrict__ edge_dst) {
    extern __shared__ float sm[];
    float* sW = sm;                     // 64 x 128 (this segment)
    float* sH = sm + 8192;              // 64 x 64 [k][e]
    int*   sSrc = (int*)(sm + 12288);   // 64
    int*   sDst = sSrc + 64;            // 64
    float4* sY  = (float4*)(sDst + 64); // 64

    const int tid = threadIdx.x;
    const int seg = blockIdx.y;
    const float f0 = 0.03125f;                       // (1/8)*(1/4)
    const float f3 = 0.03125f * 0.5773502691896258f; // * 1/sqrt(3)

    for (int i = tid; i < 64 * 128; i += 256) {
        int k = i >> 7, j = seg * 128 + (i & 127);
        float w;
        if (j < 128)      w = Wtp0[k * 128 + j] * f0;
        else if (j < 256) w = Wtp1[k * 128 + (j - 128)] * f0;
        else if (j < 320) w = Wtp2[k * 64 + (j - 256)] * f0;
        else              w = Wtp3[k * 64 + (j - 320)] * f3;
        sW[i] = w;
    }
    const int B = blockIdx.x * 64;
    for (int i = tid; i < 4096; i += 256)
        sH[i] = g_h[(size_t)(i >> 6) * N_EDGES + B + (i & 63)];
    if (tid < 64) {
        int e = B + tid;
        sSrc[tid] = edge_src[e];
        sDst[tid] = edge_dst[e];
        sY[tid] = *(const float4*)&edge_attr[(size_t)e * 4];
    }
    __syncthreads();

    const int tx = tid & 31, ty = tid >> 5;
    const int eb = ty * 8;

    float acc[8][4];
    #pragma unroll
    for (int a = 0; a < 8; a++)
        #pragma unroll
        for (int b = 0; b < 4; b++) acc[a][b] = 0.f;

    #pragma unroll 4
    for (int k = 0; k < 64; k++) {
        float4 wv = *(const float4*)&sW[k * 128 + tx * 4];
        #pragma unroll
        for (int e2 = 0; e2 < 8; e2++) {
            float h = sH[(k << 6) + eb + e2];
            acc[e2][0] = fmaf(h, wv.x, acc[e2][0]);
            acc[e2][1] = fmaf(h, wv.y, acc[e2][1]);
            acc[e2][2] = fmaf(h, wv.z, acc[e2][2]);
            acc[e2][3] = fmaf(h, wv.w, acc[e2][3]);
        }
    }

    #pragma unroll
    for (int e2 = 0; e2 < 8; e2++) {
        const int le = eb + e2;
        const float* fr = g_feat + (size_t)sSrc[le] * 320;
        float* ar = g_agg + (size_t)sDst[le] * 768;
        float4 yv = sY[le];  // y0 = yv.x ; y1 = (yv.y, yv.z, yv.w)
        float w0 = acc[e2][0], w1 = acc[e2][1], w2 = acc[e2][2], w3 = acc[e2][3];
        if (seg == 0) {                    // mid0a = w * e0 * y0
            int j = tx * 4;
            float4 e0v = *(const float4*)(fr + j);
            red4(ar + j, w0 * e0v.x * yv.x, w1 * e0v.y * yv.x,
                         w2 * e0v.z * yv.x, w3 * e0v.w * yv.x);
        } else if (seg == 1) {             // mid1a = w * e0 * y1_i (SoA)
            int u = tx * 4;
            float4 e0v = *(const float4*)(fr + u);
            float t0 = w0 * e0v.x, t1 = w1 * e0v.y, t2 = w2 * e0v.z, t3 = w3 * e0v.w;
            red4(ar + 192 + u,       t0 * yv.y, t1 * yv.y, t2 * yv.y, t3 * yv.y);
            red4(ar + 192 + 128 + u, t0 * yv.z, t1 * yv.z, t2 * yv.z, t3 * yv.z);
            red4(ar + 192 + 256 + u, t0 * yv.w, t1 * yv.w, t2 * yv.w, t3 * yv.w);
        } else if (tx < 16) {              // mid1b = w * e1_i * y0 (SoA)
            int u = tx * 4;
            const float* p = fr + 128 + 3 * u;
            float4 a = *(const float4*)p;
            float4 b = *(const float4*)(p + 4);
            float4 c = *(const float4*)(p + 8);
            float y0 = yv.x;
            red4(ar + 576 + u,       w0 * a.x * y0, w1 * a.w * y0, w2 * b.z * y0, w3 * c.y * y0);
            red4(ar + 576 + 64 + u,  w0 * a.y * y0, w1 * b.x * y0, w2 * b.w * y0, w3 * c.z * y0);
            red4(ar + 576 + 128 + u, w0 * a.z * y0, w1 * b.y * y0, w2 * c.x * y0, w3 * c.w * y0);
        } else {                           // mid0b = w * dot(e1, y1)
            int u = (tx - 16) * 4;
            const float* p = fr + 128 + 3 * u;
            float4 a = *(const float4*)p;
            float4 b = *(const float4*)(p + 4);
            float4 c = *(const float4*)(p + 8);
            float d0 = a.x * yv.y + a.y * yv.z + a.z * yv.w;
            float d1 = a.w * yv.y + b.x * yv.z + b.y * yv.w;
            float d2 = b.z * yv.y + b.w * yv.z + c.x * yv.w;
            float d3 = c.y * yv.y + c.z * yv.z + c.w * yv.w;
            red4(ar + 128 + u, w0 * d0, w1 * d1, w2 * d2, w3 * d3);
        }
    }
}

// ---------------- kernel 4: node post (streaming-W GEMMs + combine) ----------------
// blocks [0,625): conv0 — 16 nodes (2 halves of 8), u in [0,128)
// blocks [625,1250): conv1 — 16 nodes (4 quarters of 4), u in [0,64), 3 comps
__global__ __launch_bounds__(256) void node_post_kernel(const float* __restrict__ Wo0,
                                 const float* __restrict__ Wo1,
                                 float* __restrict__ out) {
    extern __shared__ float sm[];
    const int tid = threadIdx.x;
    const float so = 0.3826834323650898f * 0.07216878364870323f; // sin(pi/8)/sqrt(192)

    if (blockIdx.x < 625) {
        // ---- conv0 ----
        const int nb = blockIdx.x * 16;
        float* zs = sm;                    // 16 x 192
        for (int idx = tid; idx < 16 * 192; idx += 256)
            zs[idx] = g_agg[(size_t)(nb + idx / 192) * 768 + (idx % 192)];
        __syncthreads();

        const int nh = tid >> 7;   // 8 nodes
        const int u  = tid & 127;
        float acc[8];
        #pragma unroll
        for (int n = 0; n < 8; n++) acc[n] = 0.f;
        #pragma unroll 4
        for (int v = 0; v < 192; v++) {
            float w = Wo0[v * 128 + u] * so;
            #pragma unroll
            for (int n = 0; n < 8; n++)
                acc[n] = fmaf(zs[(nh * 8 + n) * 192 + v], w, acc[n]);
        }
        #pragma unroll
        for (int n = 0; n < 8; n++) {
            size_t o = (size_t)(nb + nh * 8 + n) * 320 + u;
            out[o] = g_self[o] + acc[n];
        }
    } else {
        // ---- conv1 ----
        const int nb = (blockIdx.x - 625) * 16;
        float* zs = sm;                    // 16 x 3 x 192 : [n*576 + i*192 + v]
        for (int idx = tid; idx < 16 * 576; idx += 256) {
            int n = idx / 576, r = idx % 576;
            int i = r / 192, v = r % 192;
            size_t base = (size_t)(nb + n) * 768;
            zs[idx] = (v < 128) ? g_agg[base + 192 + i * 128 + v]
                                : g_agg[base + 576 + i * 64 + (v - 128)];
        }
        __syncthreads();

        const int nq = tid >> 6;   // 4 nodes
        const int u  = tid & 63;
        float acc[4][3];
        #pragma unroll
        for (int n = 0; n < 4; n++)
            #pragma unroll
            for (int i = 0; i < 3; i++) acc[n][i] = 0.f;
        #pragma unroll 4
        for (int v = 0; v < 192; v++) {
            float w = Wo1[v * 64 + u] * so;
            #pragma unroll
            for (int n = 0; n < 4; n++) {
                const float* zb = &zs[(nq * 4 + n) * 576 + v];
                acc[n][0] = fmaf(zb[0],   w, acc[n][0]);
                acc[n][1] = fmaf(zb[192], w, acc[n][1]);
                acc[n][2] = fmaf(zb[384], w, acc[n][2]);
            }
        }
        #pragma unroll
        for (int n = 0; n < 4; n++)
            #pragma unroll
            for (int i = 0; i < 3; i++) {
                size_t o = (size_t)(nb + nq * 4 + n) * 320 + 128 + u * 3 + i;
                out[o] = g_self[o] + acc[n][i];
            }
    }
}

// ---------------- launch ----------------
extern "C" void kernel_launch(void* const* d_in, const int* in_sizes, int n_in,
                              void* d_out, int out_size) {
    const float* node_input = (const float*)d_in[0];
    const float* edge_attr  = (const float*)d_in[1];
    const float* edge_sc    = (const float*)d_in[2];
    const float* Wa0 = (const float*)d_in[3];
    const float* Wa1 = (const float*)d_in[4];
    const float* Wb0 = (const float*)d_in[5];
    const float* Wb1 = (const float*)d_in[6];
    const float* M1  = (const float*)d_in[7];
    const float* M2  = (const float*)d_in[8];
    const float* Wtp0 = (const float*)d_in[9];
    const float* Wtp1 = (const float*)d_in[10];
    const float* Wtp2 = (const float*)d_in[11];
    const float* Wtp3 = (const float*)d_in[12];
    const float* Wo0  = (const float*)d_in[13];
    const float* Wo1  = (const float*)d_in[14];
    const int* esrc = (const int*)d_in[15];
    const int* edst = (const int*)d_in[16];
    float* out = (float*)d_out;

    cudaFuncSetAttribute(edge_scatter_kernel, cudaFuncAttributeMaxDynamicSharedMemorySize, 50688);
    cudaFuncSetAttribute(node_post_kernel,    cudaFuncAttributeMaxDynamicSharedMemorySize, 36864);

    zero_agg_kernel<<<7500, 256>>>();
    node_pre_kernel<<<1250, 256, 12288>>>(node_input, Wa0, Wa1, Wb0, Wb1);
    edge_mlp_kernel<<<625, 256>>>(edge_sc, M1, M2);
    edge_scatter_kernel<<<dim3(2500, 3), 256, 50688>>>(edge_attr, Wtp0, Wtp1, Wtp2, Wtp3, esrc, edst);
    node_post_kernel<<<1250, 256, 36864>>>(Wo0, Wo1, out);
}

// round 13
// speedup vs baseline: 2.5377x; 1.1102x over previous
#include <cuda_runtime.h>
#include <cstdint>

#define N_NODES 10000
#define N_EDGES 160000

// ---------------- scratch ----------------
// feat per node (320): [0:128) feat0[u]; [128:320) feat1[u][i] (i fastest)
// self: same layout, pre-scaled by cos(angle)
// g_h: tiled [e/64][k][e%64]  (64x64 tiles, contiguous 16KB per edge-tile)
// g_agg per node (768): [0:128) mid0a | [128:192) mid0b | [192:576) mid1a SoA (192+i*128+u) | [576:768) mid1b SoA (576+i*64+u)
__device__ float g_feat[N_NODES * 320];
__device__ float g_self[N_NODES * 320];
__device__ float g_h[64 * N_EDGES];
__device__ float g_agg[N_NODES * 768];

#define AGG_F4   ((N_NODES * 768) / 4)   // 1,920,000 float4
#define ZERO_BLK ((AGG_F4 + 1023) / 1024) // 1875 blocks of 1024 float4

__device__ __forceinline__ float gelu_tanh(float x) {
    float x3 = x * x * x;
    return 0.5f * x * (1.0f + tanhf(0.7978845608028654f * (x + 0.044715f * x3)));
}

__device__ __forceinline__ void red4(float* p, float a, float b, float c, float d) {
    asm volatile("red.global.add.v4.f32 [%0], {%1,%2,%3,%4};"
                 :: "l"(p), "f"(a), "f"(b), "f"(c), "f"(d) : "memory");
}

// ---------------- kernel 1: node pre (streaming-W GEMMs) + fused agg-zero ----------------
// blocks [0,625): GEMM0 — 16 nodes, 256 lanes (128 feat0/Wa0 | 128 self0/Wb0)
// blocks [625,1250): GEMM1 — 16 nodes, 3 comps
// blocks [1250,1250+ZERO_BLK): zero g_agg (1024 float4 per block, full coverage)
__global__ __launch_bounds__(256) void node_pre_kernel(const float* __restrict__ node_input,
                                const float* __restrict__ Wa0,
                                const float* __restrict__ Wa1,
                                const float* __restrict__ Wb0,
                                const float* __restrict__ Wb1) {
    extern __shared__ float sm[];
    const int tid = threadIdx.x;
    const float sA0 = 0.08838834764831845f;            // 1/sqrt(128)
    const float sA1 = 0.125f;                          // 1/sqrt(64)
    const float cc  = 0.9238795325112867f;             // cos(pi/8)

    if (blockIdx.x >= 1250) {
        // ---- zero g_agg (full coverage: ZERO_BLK blocks x 1024 float4) ----
        float4* p = (float4*)g_agg;
        int base = (blockIdx.x - 1250) * 1024 + tid;
        #pragma unroll
        for (int r = 0; r < 4; r++) {
            int i = base + r * 256;
            if (i < AGG_F4)
                p[i] = make_float4(0.f, 0.f, 0.f, 0.f);
        }
        return;
    }

    if (blockIdx.x < 625) {
        // ---- GEMM0 ----
        const int nb = blockIdx.x * 16;
        float* xs0 = sm;                               // 16 x 128
        for (int i = tid; i < 16 * 128; i += 256)
            xs0[i] = node_input[(size_t)(nb + (i >> 7)) * 320 + (i & 127)];
        __syncthreads();

        const int sel = tid >> 7;          // 0: Wa0->feat, 1: Wb0->self
        const int u   = tid & 127;
        const float* W = sel ? Wb0 : Wa0;
        const float sc = sel ? (cc * sA0) : sA0;
        float acc[16];
        #pragma unroll
        for (int n = 0; n < 16; n++) acc[n] = 0.f;
        #pragma unroll 8
        for (int v = 0; v < 128; v++) {
            float w = W[v * 128 + u];
            #pragma unroll
            for (int n = 0; n < 16; n++)
                acc[n] = fmaf(xs0[n * 128 + v], w, acc[n]);
        }
        float* dst = sel ? g_self : g_feat;
        #pragma unroll
        for (int n = 0; n < 16; n++)
            dst[(size_t)(nb + n) * 320 + u] = acc[n] * sc;
    } else {
        // ---- GEMM1 ----
        const int nb = (blockIdx.x - 625) * 16;
        float* xs1 = sm;                               // 16 x 3 x 64 : [n*192 + i*64 + v]
        for (int idx = tid; idx < 16 * 192; idx += 256) {
            int n = idx / 192, r = idx % 192;
            int i = r >> 6, v = r & 63;
            xs1[idx] = node_input[(size_t)(nb + n) * 320 + 128 + v * 3 + i];
        }
        __syncthreads();

        const int nh  = tid >> 7;          // node half: 8 nodes
        const int lcl = tid & 127;
        const int sel = lcl >> 6;          // 0: Wa1->feat, 1: Wb1->self
        const int u   = lcl & 63;
        const float* W = sel ? Wb1 : Wa1;
        const float sc = sel ? (cc * sA1) : sA1;
        float acc[8][3];
        #pragma unroll
        for (int n = 0; n < 8; n++)
            #pragma unroll
            for (int i = 0; i < 3; i++) acc[n][i] = 0.f;
        #pragma unroll 8
        for (int v = 0; v < 64; v++) {
            float w = W[v * 64 + u];
            #pragma unroll
            for (int n = 0; n < 8; n++) {
                const float* xb = &xs1[(nh * 8 + n) * 192 + v];
                acc[n][0] = fmaf(xb[0],   w, acc[n][0]);
                acc[n][1] = fmaf(xb[64],  w, acc[n][1]);
                acc[n][2] = fmaf(xb[128], w, acc[n][2]);
            }
        }
        float* dst = sel ? g_self : g_feat;
        #pragma unroll
        for (int n = 0; n < 8; n++)
            #pragma unroll
            for (int i = 0; i < 3; i++)
                dst[(size_t)(nb + nh * 8 + n) * 320 + 128 + u * 3 + i] = acc[n][i] * sc;
    }
}

// ---------------- kernel 2: edge MLP ----------------
// writes g_h tiled: g_h[(e>>6)*4096 + k*64 + (e&63)]
__global__ __launch_bounds__(256) void edge_mlp_kernel(const float* __restrict__ es_attr,
                                const float* __restrict__ M1,
                                const float* __restrict__ M2) {
    __shared__ float sM1[8 * 64];
    __shared__ float sM2[64 * 64];
    const int tid = threadIdx.x;
    const float s1 = 0.3535533905932738f;  // 1/sqrt(8)
    const float s2 = 0.125f;
    for (int i = tid; i < 512; i += 256)  sM1[i] = M1[i] * s1;
    for (int i = tid; i < 4096; i += 256) sM2[i] = M2[i] * s2;
    __syncthreads();

    const int e = blockIdx.x * 256 + tid;
    float* hout = g_h + (size_t)(e >> 6) * 4096 + (e & 63);
    float es[8];
    {
        float4 p0 = *(const float4*)&es_attr[(size_t)e * 8];
        float4 p1 = *(const float4*)&es_attr[(size_t)e * 8 + 4];
        es[0] = p0.x; es[1] = p0.y; es[2] = p0.z; es[3] = p0.w;
        es[4] = p1.x; es[5] = p1.y; es[6] = p1.z; es[7] = p1.w;
    }
    float h1[64];
    #pragma unroll
    for (int k = 0; k < 64; k += 4) {
        float ax = 0.f, ay = 0.f, az = 0.f, aw = 0.f;
        #pragma unroll
        for (int j = 0; j < 8; j++) {
            float4 w = *(const float4*)&sM1[j * 64 + k];
            ax = fmaf(es[j], w.x, ax); ay = fmaf(es[j], w.y, ay);
            az = fmaf(es[j], w.z, az); aw = fmaf(es[j], w.w, aw);
        }
        h1[k + 0] = gelu_tanh(ax); h1[k + 1] = gelu_tanh(ay);
        h1[k + 2] = gelu_tanh(az); h1[k + 3] = gelu_tanh(aw);
    }
    #pragma unroll
    for (int k = 0; k < 64; k += 4) {
        float ax = 0.f, ay = 0.f, az = 0.f, aw = 0.f;
        #pragma unroll
        for (int j = 0; j < 64; j++) {
            float4 w = *(const float4*)&sM2[j * 64 + k];
            ax = fmaf(h1[j], w.x, ax); ay = fmaf(h1[j], w.y, ay);
            az = fmaf(h1[j], w.z, az); aw = fmaf(h1[j], w.w, aw);
        }
        hout[(k + 0) * 64] = gelu_tanh(ax);
        hout[(k + 1) * 64] = gelu_tanh(ay);
        hout[(k + 2) * 64] = gelu_tanh(az);
        hout[(k + 3) * 64] = gelu_tanh(aw);
    }
}

// ---------------- kernel 3: fused w-GEMM + TP + scatter ----------------
// grid = (1250, 3): 2 edge-tiles of 64 per block; blockIdx.y = col segment of 128
// block 256: tx = tid&31 -> 4 cols, ty = tid>>5 -> 8 edges
__global__ __launch_bounds__(256, 4)
void edge_scatter_kernel(const float* __restrict__ edge_attr,
                         const float* __restrict__ Wtp0,
                         const float* __restrict__ Wtp1,
                         const float* __restrict__ Wtp2,
                         const float* __restrict__ Wtp3,
                         const int* __restrict__ edge_src,
                         const int* __restrict__ edge_dst) {
    extern __shared__ float sm[];
    float* sW = sm;                     // 64 x 128 (this segment)
    float* sH = sm + 8192;              // 64 x 64 [k][e]
    int*   sSrc = (int*)(sm + 12288);   // 64
    int*   sDst = sSrc + 64;            // 64
    float4* sY  = (float4*)(sDst + 64); // 64

    const int tid = threadIdx.x;
    const int seg = blockIdx.y;
    const float f0 = 0.03125f;                       // (1/8)*(1/4)
    const float f3 = 0.03125f * 0.5773502691896258f; // * 1/sqrt(3)

    for (int i = tid; i < 64 * 128; i += 256) {
        int k = i >> 7, j = seg * 128 + (i & 127);
        float w;
        if (j < 128)      w = Wtp0[k * 128 + j] * f0;
        else if (j < 256) w = Wtp1[k * 128 + (j - 128)] * f0;
        else if (j < 320) w = Wtp2[k * 64 + (j - 256)] * f0;
        else              w = Wtp3[k * 64 + (j - 320)] * f3;
        sW[i] = w;
    }

    const int tx = tid & 31, ty = tid >> 5;
    const int eb = ty * 8;

    for (int t = 0; t < 2; t++) {
        const int B = blockIdx.x * 128 + t * 64;
        __syncthreads();
        {
            const float4* hsrc = (const float4*)(g_h + (size_t)(B >> 6) * 4096);
            float4* hdst = (float4*)sH;
            for (int i = tid; i < 1024; i += 256) hdst[i] = hsrc[i];
            if (tid < 64) {
                int e = B + tid;
                sSrc[tid] = edge_src[e];
                sDst[tid] = edge_dst[e];
                sY[tid] = *(const float4*)&edge_attr[(size_t)e * 4];
            }
        }
        __syncthreads();

        float acc[8][4];
        #pragma unroll
        for (int a = 0; a < 8; a++)
            #pragma unroll
            for (int b = 0; b < 4; b++) acc[a][b] = 0.f;

        #pragma unroll 4
        for (int k = 0; k < 64; k++) {
            float4 wv = *(const float4*)&sW[k * 128 + tx * 4];
            float4 h0 = *(const float4*)&sH[(k << 6) + eb];
            float4 h1 = *(const float4*)&sH[(k << 6) + eb + 4];
            acc[0][0] = fmaf(h0.x, wv.x, acc[0][0]);
            acc[0][1] = fmaf(h0.x, wv.y, acc[0][1]);
            acc[0][2] = fmaf(h0.x, wv.z, acc[0][2]);
            acc[0][3] = fmaf(h0.x, wv.w, acc[0][3]);
            acc[1][0] = fmaf(h0.y, wv.x, acc[1][0]);
            acc[1][1] = fmaf(h0.y, wv.y, acc[1][1]);
            acc[1][2] = fmaf(h0.y, wv.z, acc[1][2]);
            acc[1][3] = fmaf(h0.y, wv.w, acc[1][3]);
            acc[2][0] = fmaf(h0.z, wv.x, acc[2][0]);
            acc[2][1] = fmaf(h0.z, wv.y, acc[2][1]);
            acc[2][2] = fmaf(h0.z, wv.z, acc[2][2]);
            acc[2][3] = fmaf(h0.z, wv.w, acc[2][3]);
            acc[3][0] = fmaf(h0.w, wv.x, acc[3][0]);
            acc[3][1] = fmaf(h0.w, wv.y, acc[3][1]);
            acc[3][2] = fmaf(h0.w, wv.z, acc[3][2]);
            acc[3][3] = fmaf(h0.w, wv.w, acc[3][3]);
            acc[4][0] = fmaf(h1.x, wv.x, acc[4][0]);
            acc[4][1] = fmaf(h1.x, wv.y, acc[4][1]);
            acc[4][2] = fmaf(h1.x, wv.z, acc[4][2]);
            acc[4][3] = fmaf(h1.x, wv.w, acc[4][3]);
            acc[5][0] = fmaf(h1.y, wv.x, acc[5][0]);
            acc[5][1] = fmaf(h1.y, wv.y, acc[5][1]);
            acc[5][2] = fmaf(h1.y, wv.z, acc[5][2]);
            acc[5][3] = fmaf(h1.y, wv.w, acc[5][3]);
            acc[6][0] = fmaf(h1.z, wv.x, acc[6][0]);
            acc[6][1] = fmaf(h1.z, wv.y, acc[6][1]);
            acc[6][2] = fmaf(h1.z, wv.z, acc[6][2]);
            acc[6][3] = fmaf(h1.z, wv.w, acc[6][3]);
            acc[7][0] = fmaf(h1.w, wv.x, acc[7][0]);
            acc[7][1] = fmaf(h1.w, wv.y, acc[7][1]);
            acc[7][2] = fmaf(h1.w, wv.z, acc[7][2]);
            acc[7][3] = fmaf(h1.w, wv.w, acc[7][3]);
        }

        #pragma unroll
        for (int e2 = 0; e2 < 8; e2++) {
            const int le = eb + e2;
            const float* fr = g_feat + (size_t)sSrc[le] * 320;
            float* ar = g_agg + (size_t)sDst[le] * 768;
            float4 yv = sY[le];  // y0 = yv.x ; y1 = (yv.y, yv.z, yv.w)
            float w0 = acc[e2][0], w1 = acc[e2][1], w2 = acc[e2][2], w3 = acc[e2][3];
            if (seg == 0) {                    // mid0a = w * e0 * y0
                int j = tx * 4;
                float4 e0v = *(const float4*)(fr + j);
                red4(ar + j, w0 * e0v.x * yv.x, w1 * e0v.y * yv.x,
                             w2 * e0v.z * yv.x, w3 * e0v.w * yv.x);
            } else if (seg == 1) {             // mid1a = w * e0 * y1_i (SoA)
                int u = tx * 4;
                float4 e0v = *(const float4*)(fr + u);
                float t0 = w0 * e0v.x, t1 = w1 * e0v.y, t2 = w2 * e0v.z, t3 = w3 * e0v.w;
                red4(ar + 192 + u,       t0 * yv.y, t1 * yv.y, t2 * yv.y, t3 * yv.y);
                red4(ar + 192 + 128 + u, t0 * yv.z, t1 * yv.z, t2 * yv.z, t3 * yv.z);
                red4(ar + 192 + 256 + u, t0 * yv.w, t1 * yv.w, t2 * yv.w, t3 * yv.w);
            } else if (tx < 16) {              // mid1b = w * e1_i * y0 (SoA)
                int u = tx * 4;
                const float* p = fr + 128 + 3 * u;
                float4 a = *(const float4*)p;
                float4 b = *(const float4*)(p + 4);
                float4 c = *(const float4*)(p + 8);
                float y0 = yv.x;
                red4(ar + 576 + u,       w0 * a.x * y0, w1 * a.w * y0, w2 * b.z * y0, w3 * c.y * y0);
                red4(ar + 576 + 64 + u,  w0 * a.y * y0, w1 * b.x * y0, w2 * b.w * y0, w3 * c.z * y0);
                red4(ar + 576 + 128 + u, w0 * a.z * y0, w1 * b.y * y0, w2 * c.x * y0, w3 * c.w * y0);
            } else {                           // mid0b = w * dot(e1, y1)
                int u = (tx - 16) * 4;
                const float* p = fr + 128 + 3 * u;
                float4 a = *(const float4*)p;
                float4 b = *(const float4*)(p + 4);
                float4 c = *(const float4*)(p + 8);
                float d0 = a.x * yv.y + a.y * yv.z + a.z * yv.w;
                float d1 = a.w * yv.y + b.x * yv.z + b.y * yv.w;
                float d2 = b.z * yv.y + b.w * yv.z + c.x * yv.w;
                float d3 = c.y * yv.y + c.z * yv.z + c.w * yv.w;
                red4(ar + 128 + u, w0 * d0, w1 * d1, w2 * d2, w3 * d3);
            }
        }
    }
}

// ---------------- kernel 4: node post (streaming-W GEMMs + combine) ----------------
__global__ __launch_bounds__(256) void node_post_kernel(const float* __restrict__ Wo0,
                                 const float* __restrict__ Wo1,
                                 float* __restrict__ out) {
    extern __shared__ float sm[];
    const int tid = threadIdx.x;
    const float so = 0.3826834323650898f * 0.07216878364870323f; // sin(pi/8)/sqrt(192)

    if (blockIdx.x < 625) {
        // ---- conv0 ----
        const int nb = blockIdx.x * 16;
        float* zs = sm;                    // 16 x 192
        for (int idx = tid; idx < 16 * 192; idx += 256)
            zs[idx] = g_agg[(size_t)(nb + idx / 192) * 768 + (idx % 192)];
        __syncthreads();

        const int nh = tid >> 7;   // 8 nodes
        const int u  = tid & 127;
        float acc[8];
        #pragma unroll
        for (int n = 0; n < 8; n++) acc[n] = 0.f;
        #pragma unroll 8
        for (int v = 0; v < 192; v++) {
            float w = Wo0[v * 128 + u];
            #pragma unroll
            for (int n = 0; n < 8; n++)
                acc[n] = fmaf(zs[(nh * 8 + n) * 192 + v], w, acc[n]);
        }
        #pragma unroll
        for (int n = 0; n < 8; n++) {
            size_t o = (size_t)(nb + nh * 8 + n) * 320 + u;
            out[o] = g_self[o] + acc[n] * so;
        }
    } else {
        // ---- conv1 ----
        const int nb = (blockIdx.x - 625) * 16;
        float* zs = sm;                    // 16 x 3 x 192 : [n*576 + i*192 + v]
        for (int idx = tid; idx < 16 * 576; idx += 256) {
            int n = idx / 576, r = idx % 576;
            int i = r / 192, v = r % 192;
            size_t base = (size_t)(nb + n) * 768;
            zs[idx] = (v < 128) ? g_agg[base + 192 + i * 128 + v]
                                : g_agg[base + 576 + i * 64 + (v - 128)];
        }
        __syncthreads();

        const int nq = tid >> 6;   // 4 nodes
        const int u  = tid & 63;
        float acc[4][3];
        #pragma unroll
        for (int n = 0; n < 4; n++)
            #pragma unroll
            for (int i = 0; i < 3; i++) acc[n][i] = 0.f;
        #pragma unroll 8
        for (int v = 0; v < 192; v++) {
            float w = Wo1[v * 64 + u];
            #pragma unroll
            for (int n = 0; n < 4; n++) {
                const float* zb = &zs[(nq * 4 + n) * 576 + v];
                acc[n][0] = fmaf(zb[0],   w, acc[n][0]);
                acc[n][1] = fmaf(zb[192], w, acc[n][1]);
                acc[n][2] = fmaf(zb[384], w, acc[n][2]);
            }
        }
        #pragma unroll
        for (int n = 0; n < 4; n++)
            #pragma unroll
            for (int i = 0; i < 3; i++) {
                size_t o = (size_t)(nb + nq * 4 + n) * 320 + 128 + u * 3 + i;
                out[o] = g_self[o] + acc[n][i] * so;
            }
    }
}

// ---------------- launch ----------------
extern "C" void kernel_launch(void* const* d_in, const int* in_sizes, int n_in,
                              void* d_out, int out_size) {
    const float* node_input = (const float*)d_in[0];
    const float* edge_attr  = (const float*)d_in[1];
    const float* edge_sc    = (const float*)d_in[2];
    const float* Wa0 = (const float*)d_in[3];
    const float* Wa1 = (const float*)d_in[4];
    const float* Wb0 = (const float*)d_in[5];
    const float* Wb1 = (const float*)d_in[6];
    const float* M1  = (const float*)d_in[7];
    const float* M2  = (const float*)d_in[8];
    const float* Wtp0 = (const float*)d_in[9];
    const float* Wtp1 = (const float*)d_in[10];
    const float* Wtp2 = (const float*)d_in[11];
    const float* Wtp3 = (const float*)d_in[12];
    const float* Wo0  = (const float*)d_in[13];
    const float* Wo1  = (const float*)d_in[14];
    const int* esrc = (const int*)d_in[15];
    const int* edst = (const int*)d_in[16];
    float* out = (float*)d_out;

    cudaFuncSetAttribute(edge_scatter_kernel, cudaFuncAttributeMaxDynamicSharedMemorySize, 50688);
    cudaFuncSetAttribute(node_post_kernel,    cudaFuncAttributeMaxDynamicSharedMemorySize, 36864);

    node_pre_kernel<<<1250 + ZERO_BLK, 256, 12288>>>(node_input, Wa0, Wa1, Wb0, Wb1);
    edge_mlp_kernel<<<625, 256>>>(edge_sc, M1, M2);
    edge_scatter_kernel<<<dim3(1250, 3), 256, 50688>>>(edge_attr, Wtp0, Wtp1, Wtp2, Wtp3, esrc, edst);
    node_post_kernel<<<1250, 256, 36864>>>(Wo0, Wo1, out);
}

// round 15
// speedup vs baseline: 2.6367x; 1.0390x over previous
#include <cuda_runtime.h>
#include <cstdint>

#define N_NODES 10000
#define N_EDGES 160000

// ---------------- scratch ----------------
// feat per node (320): [0:128) feat0[u]; [128:320) feat1[u][i] (i fastest)
// self: same layout, pre-scaled by cos(angle)
// g_h: tiled [e/64][k][e%64]  (64x64 tiles, contiguous 16KB per edge-tile)
// g_agg per node (768): [0:128) mid0a | [128:192) mid0b | [192:576) mid1a SoA (192+i*128+u) | [576:768) mid1b SoA (576+i*64+u)
__device__ float g_feat[N_NODES * 320];
__device__ float g_self[N_NODES * 320];
__device__ float g_h[64 * N_EDGES];
__device__ float g_agg[N_NODES * 768];

#define AGG_F4   ((N_NODES * 768) / 4)    // 1,920,000 float4
#define ZERO_BLK ((AGG_F4 + 1023) / 1024) // 1875 blocks of 1024 float4

__device__ __forceinline__ float gelu_tanh(float x) {
    float x3 = x * x * x;
    return 0.5f * x * (1.0f + tanhf(0.7978845608028654f * (x + 0.044715f * x3)));
}

__device__ __forceinline__ void red4(float* p, float a, float b, float c, float d) {
    asm volatile("red.global.add.v4.f32 [%0], {%1,%2,%3,%4};"
                 :: "l"(p), "f"(a), "f"(b), "f"(c), "f"(d) : "memory");
}

// ---------------- kernel 1: node pre (streaming-W GEMMs) + fused agg-zero ----------------
__global__ __launch_bounds__(256) void node_pre_kernel(const float* __restrict__ node_input,
                                const float* __restrict__ Wa0,
                                const float* __restrict__ Wa1,
                                const float* __restrict__ Wb0,
                                const float* __restrict__ Wb1) {
    extern __shared__ float sm[];
    const int tid = threadIdx.x;
    const float sA0 = 0.08838834764831845f;            // 1/sqrt(128)
    const float sA1 = 0.125f;                          // 1/sqrt(64)
    const float cc  = 0.9238795325112867f;             // cos(pi/8)

    if (blockIdx.x >= 1250) {
        // ---- zero g_agg (full coverage) ----
        float4* p = (float4*)g_agg;
        int base = (blockIdx.x - 1250) * 1024 + tid;
        #pragma unroll
        for (int r = 0; r < 4; r++) {
            int i = base + r * 256;
            if (i < AGG_F4)
                p[i] = make_float4(0.f, 0.f, 0.f, 0.f);
        }
        return;
    }

    if (blockIdx.x < 625) {
        // ---- GEMM0: 16 nodes, u in [0,128), two weight sets ----
        const int nb = blockIdx.x * 16;
        float* xs0 = sm;                               // 16 x 128
        for (int i = tid; i < 16 * 128; i += 256)
            xs0[i] = node_input[(size_t)(nb + (i >> 7)) * 320 + (i & 127)];
        __syncthreads();

        const int sel = tid >> 7;          // 0: Wa0->feat, 1: Wb0->self
        const int u   = tid & 127;
        const float* W = sel ? Wb0 : Wa0;
        const float sc = sel ? (cc * sA0) : sA0;
        float acc[16];
        #pragma unroll
        for (int n = 0; n < 16; n++) acc[n] = 0.f;
        #pragma unroll 2
        for (int v = 0; v < 128; v += 4) {
            float w0 = W[(v + 0) * 128 + u];
            float w1 = W[(v + 1) * 128 + u];
            float w2 = W[(v + 2) * 128 + u];
            float w3 = W[(v + 3) * 128 + u];
            #pragma unroll
            for (int n = 0; n < 16; n++) {
                float4 xq = *(const float4*)&xs0[n * 128 + v];
                acc[n] = fmaf(xq.x, w0, acc[n]);
                acc[n] = fmaf(xq.y, w1, acc[n]);
                acc[n] = fmaf(xq.z, w2, acc[n]);
                acc[n] = fmaf(xq.w, w3, acc[n]);
            }
        }
        float* dst = sel ? g_self : g_feat;
        #pragma unroll
        for (int n = 0; n < 16; n++)
            dst[(size_t)(nb + n) * 320 + u] = acc[n] * sc;
    } else {
        // ---- GEMM1: 16 nodes (2 halves of 8), u in [0,64), 3 comps ----
        const int nb = (blockIdx.x - 625) * 16;
        float* xs1 = sm;                               // 16 x 3 x 64 : [n*192 + i*64 + v]
        for (int idx = tid; idx < 16 * 192; idx += 256) {
            int n = idx / 192, r = idx % 192;
            int i = r >> 6, v = r & 63;
            xs1[idx] = node_input[(size_t)(nb + n) * 320 + 128 + v * 3 + i];
        }
        __syncthreads();

        const int nh  = tid >> 7;          // node half: 8 nodes
        const int lcl = tid & 127;
        const int sel = lcl >> 6;          // 0: Wa1->feat, 1: Wb1->self
        const int u   = lcl & 63;
        const float* W = sel ? Wb1 : Wa1;
        const float sc = sel ? (cc * sA1) : sA1;
        float acc[8][3];
        #pragma unroll
        for (int n = 0; n < 8; n++)
            #pragma unroll
            for (int i = 0; i < 3; i++) acc[n][i] = 0.f;
        #pragma unroll 2
        for (int v = 0; v < 64; v += 4) {
            float w0 = W[(v + 0) * 64 + u];
            float w1 = W[(v + 1) * 64 + u];
            float w2 = W[(v + 2) * 64 + u];
            float w3 = W[(v + 3) * 64 + u];
            #pragma unroll
            for (int n = 0; n < 8; n++) {
                const float* xb = &xs1[(nh * 8 + n) * 192 + v];
                #pragma unroll
                for (int i = 0; i < 3; i++) {
                    float4 xq = *(const float4*)&xb[i * 64];
                    acc[n][i] = fmaf(xq.x, w0, acc[n][i]);
                    acc[n][i] = fmaf(xq.y, w1, acc[n][i]);
                    acc[n][i] = fmaf(xq.z, w2, acc[n][i]);
                    acc[n][i] = fmaf(xq.w, w3, acc[n][i]);
                }
            }
        }
        float* dst = sel ? g_self : g_feat;
        #pragma unroll
        for (int n = 0; n < 8; n++)
            #pragma unroll
            for (int i = 0; i < 3; i++)
                dst[(size_t)(nb + nh * 8 + n) * 320 + 128 + u * 3 + i] = acc[n][i] * sc;
    }
}

// ---------------- kernel 2: edge MLP ----------------
// writes g_h tiled: g_h[(e>>6)*4096 + k*64 + (e&63)]
__global__ __launch_bounds__(256) void edge_mlp_kernel(const float* __restrict__ es_attr,
                                const float* __restrict__ M1,
                                const float* __restrict__ M2) {
    __shared__ float sM1[8 * 64];
    __shared__ float sM2[64 * 64];
    const int tid = threadIdx.x;
    const float s1 = 0.3535533905932738f;  // 1/sqrt(8)
    const float s2 = 0.125f;
    for (int i = tid; i < 512; i += 256)  sM1[i] = M1[i] * s1;
    for (int i = tid; i < 4096; i += 256) sM2[i] = M2[i] * s2;
    __syncthreads();

    const int e = blockIdx.x * 256 + tid;
    float* hout = g_h + (size_t)(e >> 6) * 4096 + (e & 63);
    float es[8];
    {
        float4 p0 = *(const float4*)&es_attr[(size_t)e * 8];
        float4 p1 = *(const float4*)&es_attr[(size_t)e * 8 + 4];
        es[0] = p0.x; es[1] = p0.y; es[2] = p0.z; es[3] = p0.w;
        es[4] = p1.x; es[5] = p1.y; es[6] = p1.z; es[7] = p1.w;
    }
    float h1[64];
    #pragma unroll
    for (int k = 0; k < 64; k += 4) {
        float ax = 0.f, ay = 0.f, az = 0.f, aw = 0.f;
        #pragma unroll
        for (int j = 0; j < 8; j++) {
            float4 w = *(const float4*)&sM1[j * 64 + k];
            ax = fmaf(es[j], w.x, ax); ay = fmaf(es[j], w.y, ay);
            az = fmaf(es[j], w.z, az); aw = fmaf(es[j], w.w, aw);
        }
        h1[k + 0] = gelu_tanh(ax); h1[k + 1] = gelu_tanh(ay);
        h1[k + 2] = gelu_tanh(az); h1[k + 3] = gelu_tanh(aw);
    }
    #pragma unroll
    for (int k = 0; k < 64; k += 4) {
        float ax = 0.f, ay = 0.f, az = 0.f, aw = 0.f;
        #pragma unroll
        for (int j = 0; j < 64; j++) {
            float4 w = *(const float4*)&sM2[j * 64 + k];
            ax = fmaf(h1[j], w.x, ax); ay = fmaf(h1[j], w.y, ay);
            az = fmaf(h1[j], w.z, az); aw = fmaf(h1[j], w.w, aw);
        }
        hout[(k + 0) * 64] = gelu_tanh(ax);
        hout[(k + 1) * 64] = gelu_tanh(ay);
        hout[(k + 2) * 64] = gelu_tanh(az);
        hout[(k + 3) * 64] = gelu_tanh(aw);
    }
}

// ---------------- kernel 3: fused w-GEMM + TP + scatter ----------------
// grid = (625, 3): 4 edge-tiles of 64 per block; blockIdx.y = col segment of 128
// block 256: tx = tid&31 -> 4 cols, ty = tid>>5 -> 8 edges
__global__ __launch_bounds__(256, 4)
void edge_scatter_kernel(const float* __restrict__ edge_attr,
                         const float* __restrict__ Wtp0,
                         const float* __restrict__ Wtp1,
                         const float* __restrict__ Wtp2,
                         const float* __restrict__ Wtp3,
                         const int* __restrict__ edge_src,
                         const int* __restrict__ edge_dst) {
    extern __shared__ float sm[];
    float* sW = sm;                     // 64 x 128 (this segment)
    float* sH = sm + 8192;              // 64 x 64 [k][e]
    int*   sSrc = (int*)(sm + 12288);   // 64
    int*   sDst = sSrc + 64;            // 64
    float4* sY  = (float4*)(sDst + 64); // 64

    const int tid = threadIdx.x;
    const int seg = blockIdx.y;
    const float f0 = 0.03125f;                       // (1/8)*(1/4)
    const float f3 = 0.03125f * 0.5773502691896258f; // * 1/sqrt(3)

    for (int i = tid; i < 64 * 128; i += 256) {
        int k = i >> 7, j = seg * 128 + (i & 127);
        float w;
        if (j < 128)      w = Wtp0[k * 128 + j] * f0;
        else if (j < 256) w = Wtp1[k * 128 + (j - 128)] * f0;
        else if (j < 320) w = Wtp2[k * 64 + (j - 256)] * f0;
        else              w = Wtp3[k * 64 + (j - 320)] * f3;
        sW[i] = w;
    }

    const int tx = tid & 31, ty = tid >> 5;
    const int eb = ty * 8;

    for (int t = 0; t < 4; t++) {
        const int B = blockIdx.x * 256 + t * 64;
        __syncthreads();
        {
            const float4* hsrc = (const float4*)(g_h + (size_t)(B >> 6) * 4096);
            float4* hdst = (float4*)sH;
            for (int i = tid; i < 1024; i += 256) hdst[i] = hsrc[i];
            if (tid < 64) {
                int e = B + tid;
                sSrc[tid] = edge_src[e];
                sDst[tid] = edge_dst[e];
                sY[tid] = *(const float4*)&edge_attr[(size_t)e * 4];
            }
        }
        __syncthreads();

        float acc[8][4];
        #pragma unroll
        for (int a = 0; a < 8; a++)
            #pragma unroll
            for (int b = 0; b < 4; b++) acc[a][b] = 0.f;

        #pragma unroll 4
        for (int k = 0; k < 64; k++) {
            float4 wv = *(const float4*)&sW[k * 128 + tx * 4];
            float4 h0 = *(const float4*)&sH[(k << 6) + eb];
            float4 h1 = *(const float4*)&sH[(k << 6) + eb + 4];
            acc[0][0] = fmaf(h0.x, wv.x, acc[0][0]);
            acc[0][1] = fmaf(h0.x, wv.y, acc[0][1]);
            acc[0][2] = fmaf(h0.x, wv.z, acc[0][2]);
            acc[0][3] = fmaf(h0.x, wv.w, acc[0][3]);
            acc[1][0] = fmaf(h0.y, wv.x, acc[1][0]);
            acc[1][1] = fmaf(h0.y, wv.y, acc[1][1]);
            acc[1][2] = fmaf(h0.y, wv.z, acc[1][2]);
            acc[1][3] = fmaf(h0.y, wv.w, acc[1][3]);
            acc[2][0] = fmaf(h0.z, wv.x, acc[2][0]);
            acc[2][1] = fmaf(h0.z, wv.y, acc[2][1]);
            acc[2][2] = fmaf(h0.z, wv.z, acc[2][2]);
            acc[2][3] = fmaf(h0.z, wv.w, acc[2][3]);
            acc[3][0] = fmaf(h0.w, wv.x, acc[3][0]);
            acc[3][1] = fmaf(h0.w, wv.y, acc[3][1]);
            acc[3][2] = fmaf(h0.w, wv.z, acc[3][2]);
            acc[3][3] = fmaf(h0.w, wv.w, acc[3][3]);
            acc[4][0] = fmaf(h1.x, wv.x, acc[4][0]);
            acc[4][1] = fmaf(h1.x, wv.y, acc[4][1]);
            acc[4][2] = fmaf(h1.x, wv.z, acc[4][2]);
            acc[4][3] = fmaf(h1.x, wv.w, acc[4][3]);
            acc[5][0] = fmaf(h1.y, wv.x, acc[5][0]);
            acc[5][1] = fmaf(h1.y, wv.y, acc[5][1]);
            acc[5][2] = fmaf(h1.y, wv.z, acc[5][2]);
            acc[5][3] = fmaf(h1.y, wv.w, acc[5][3]);
            acc[6][0] = fmaf(h1.z, wv.x, acc[6][0]);
            acc[6][1] = fmaf(h1.z, wv.y, acc[6][1]);
            acc[6][2] = fmaf(h1.z, wv.z, acc[6][2]);
            acc[6][3] = fmaf(h1.z, wv.w, acc[6][3]);
            acc[7][0] = fmaf(h1.w, wv.x, acc[7][0]);
            acc[7][1] = fmaf(h1.w, wv.y, acc[7][1]);
            acc[7][2] = fmaf(h1.w, wv.z, acc[7][2]);
            acc[7][3] = fmaf(h1.w, wv.w, acc[7][3]);
        }

        #pragma unroll
        for (int e2 = 0; e2 < 8; e2++) {
            const int le = eb + e2;
            const float* fr = g_feat + (size_t)sSrc[le] * 320;
            float* ar = g_agg + (size_t)sDst[le] * 768;
            float4 yv = sY[le];  // y0 = yv.x ; y1 = (yv.y, yv.z, yv.w)
            float w0 = acc[e2][0], w1 = acc[e2][1], w2 = acc[e2][2], w3 = acc[e2][3];
            if (seg == 0) {                    // mid0a = w * e0 * y0
                int j = tx * 4;
                float4 e0v = *(const float4*)(fr + j);
                red4(ar + j, w0 * e0v.x * yv.x, w1 * e0v.y * yv.x,
                             w2 * e0v.z * yv.x, w3 * e0v.w * yv.x);
            } else if (seg == 1) {             // mid1a = w * e0 * y1_i (SoA)
                int u = tx * 4;
                float4 e0v = *(const float4*)(fr + u);
                float t0 = w0 * e0v.x, t1 = w1 * e0v.y, t2 = w2 * e0v.z, t3 = w3 * e0v.w;
                red4(ar + 192 + u,       t0 * yv.y, t1 * yv.y, t2 * yv.y, t3 * yv.y);
                red4(ar + 192 + 128 + u, t0 * yv.z, t1 * yv.z, t2 * yv.z, t3 * yv.z);
                red4(ar + 192 + 256 + u, t0 * yv.w, t1 * yv.w, t2 * yv.w, t3 * yv.w);
            } else if (tx < 16) {              // mid1b = w * e1_i * y0 (SoA)
                int u = tx * 4;
                const float* p = fr + 128 + 3 * u;
                float4 a = *(const float4*)p;
                float4 b = *(const float4*)(p + 4);
                float4 c = *(const float4*)(p + 8);
                float y0 = yv.x;
                red4(ar + 576 + u,       w0 * a.x * y0, w1 * a.w * y0, w2 * b.z * y0, w3 * c.y * y0);
                red4(ar + 576 + 64 + u,  w0 * a.y * y0, w1 * b.x * y0, w2 * b.w * y0, w3 * c.z * y0);
                red4(ar + 576 + 128 + u, w0 * a.z * y0, w1 * b.y * y0, w2 * c.x * y0, w3 * c.w * y0);
            } else {                           // mid0b = w * dot(e1, y1)
                int u = (tx - 16) * 4;
                const float* p = fr + 128 + 3 * u;
                float4 a = *(const float4*)p;
                float4 b = *(const float4*)(p + 4);
                float4 c = *(const float4*)(p + 8);
                float d0 = a.x * yv.y + a.y * yv.z + a.z * yv.w;
                float d1 = a.w * yv.y + b.x * yv.z + b.y * yv.w;
                float d2 = b.z * yv.y + b.w * yv.z + c.x * yv.w;
                float d3 = c.y * yv.y + c.z * yv.z + c.w * yv.w;
                red4(ar + 128 + u, w0 * d0, w1 * d1, w2 * d2, w3 * d3);
            }
        }
    }
}

// ---------------- kernel 4: node post (streaming-W GEMMs + combine) ----------------
__global__ __launch_bounds__(256) void node_post_kernel(const float* __restrict__ Wo0,
                                 const float* __restrict__ Wo1,
                                 float* __restrict__ out) {
    extern __shared__ float sm[];
    const int tid = threadIdx.x;
    const float so = 0.3826834323650898f * 0.07216878364870323f; // sin(pi/8)/sqrt(192)

    if (blockIdx.x < 625) {
        // ---- conv0 ----
        const int nb = blockIdx.x * 16;
        float* zs = sm;                    // 16 x 192
        for (int idx = tid; idx < 16 * 192; idx += 256)
            zs[idx] = g_agg[(size_t)(nb + idx / 192) * 768 + (idx % 192)];
        __syncthreads();

        const int nh = tid >> 7;   // 8 nodes
        const int u  = tid & 127;
        float acc[8];
        #pragma unroll
        for (int n = 0; n < 8; n++) acc[n] = 0.f;
        #pragma unroll 2
        for (int v = 0; v < 192; v += 4) {
            float w0 = Wo0[(v + 0) * 128 + u];
            float w1 = Wo0[(v + 1) * 128 + u];
            float w2 = Wo0[(v + 2) * 128 + u];
            float w3 = Wo0[(v + 3) * 128 + u];
            #pragma unroll
            for (int n = 0; n < 8; n++) {
                float4 zq = *(const float4*)&zs[(nh * 8 + n) * 192 + v];
                acc[n] = fmaf(zq.x, w0, acc[n]);
                acc[n] = fmaf(zq.y, w1, acc[n]);
                acc[n] = fmaf(zq.z, w2, acc[n]);
                acc[n] = fmaf(zq.w, w3, acc[n]);
            }
        }
        #pragma unroll
        for (int n = 0; n < 8; n++) {
            size_t o = (size_t)(nb + nh * 8 + n) * 320 + u;
            out[o] = g_self[o] + acc[n] * so;
        }
    } else {
        // ---- conv1 ----
        const int nb = (blockIdx.x - 625) * 16;
        float* zs = sm;                    // 16 x 3 x 192 : [n*576 + i*192 + v]
        for (int idx = tid; idx < 16 * 576; idx += 256) {
            int n = idx / 576, r = idx % 576;
            int i = r / 192, v = r % 192;
            size_t base = (size_t)(nb + n) * 768;
            zs[idx] = (v < 128) ? g_agg[base + 192 + i * 128 + v]
                                : g_agg[base + 576 + i * 64 + (v - 128)];
        }
        __syncthreads();

        const int nq = tid >> 6;   // 4 nodes
        const int u  = tid & 63;
        float acc[4][3];
        #pragma unroll
        for (int n = 0; n < 4; n++)
            #pragma unroll
            for (int i = 0; i < 3; i++) acc[n][i] = 0.f;
        #pragma unroll 2
        for (int v = 0; v < 192; v += 4) {
            float w0 = Wo1[(v + 0) * 64 + u];
            float w1 = Wo1[(v + 1) * 64 + u];
            float w2 = Wo1[(v + 2) * 64 + u];
            float w3 = Wo1[(v + 3) * 64 + u];
            #pragma unroll
            for (int n = 0; n < 4; n++) {
                const float* zb = &zs[(nq * 4 + n) * 576 + v];
                #pragma unroll
                for (int i = 0; i < 3; i++) {
                    float4 zq = *(const float4*)&zb[i * 192];
                    acc[n][i] = fmaf(zq.x, w0, acc[n][i]);
                    acc[n][i] = fmaf(zq.y, w1, acc[n][i]);
                    acc[n][i] = fmaf(zq.z, w2, acc[n][i]);
                    acc[n][i] = fmaf(zq.w, w3, acc[n][i]);
                }
            }
        }
        #pragma unroll
        for (int n = 0; n < 4; n++)
            #pragma unroll
            for (int i = 0; i < 3; i++) {
                size_t o = (size_t)(nb + nq * 4 + n) * 320 + 128 + u * 3 + i;
                out[o] = g_self[o] + acc[n][i] * so;
            }
    }
}

// ---------------- launch ----------------
extern "C" void kernel_launch(void* const* d_in, const int* in_sizes, int n_in,
                              void* d_out, int out_size) {
    const float* node_input = (const float*)d_in[0];
    const float* edge_attr  = (const float*)d_in[1];
    const float* edge_sc    = (const float*)d_in[2];
    const float* Wa0 = (const float*)d_in[3];
    const float* Wa1 = (const float*)d_in[4];
    const float* Wb0 = (const float*)d_in[5];
    const float* Wb1 = (const float*)d_in[6];
    const float* M1  = (const float*)d_in[7];
    const float* M2  = (const float*)d_in[8];
    const float* Wtp0 = (const float*)d_in[9];
    const float* Wtp1 = (const float*)d_in[10];
    const float* Wtp2 = (const float*)d_in[11];
    const float* Wtp3 = (const float*)d_in[12];
    const float* Wo0  = (const float*)d_in[13];
    const float* Wo1  = (const float*)d_in[14];
    const int* esrc = (const int*)d_in[15];
    const int* edst = (const int*)d_in[16];
    float* out = (float*)d_out;

    cudaFuncSetAttribute(edge_scatter_kernel, cudaFuncAttributeMaxDynamicSharedMemorySize, 50688);
    cudaFuncSetAttribute(node_post_kernel,    cudaFuncAttributeMaxDynamicSharedMemorySize, 36864);

    node_pre_kernel<<<1250 + ZERO_BLK, 256, 12288>>>(node_input, Wa0, Wa1, Wb0, Wb1);
    edge_mlp_kernel<<<625, 256>>>(edge_sc, M1, M2);
    edge_scatter_kernel<<<dim3(625, 3), 256, 50688>>>(edge_attr, Wtp0, Wtp1, Wtp2, Wtp3, esrc, edst);
    node_post_kernel<<<1250, 256, 36864>>>(Wo0, Wo1, out);
}